// round 9
// baseline (speedup 1.0000x reference)
#include <cuda_runtime.h>
#include <cstdint>

// DetectPeaksTM: per-row sliding max (K=301) NMS + top-2 (value, index).
// Candidate-based (survivor == max of its aligned 128-tile). 4 rows per CTA,
// software-pipelined: while warp 0 runs row r's selection, all warps already
// have row r+1's LDG.128s in flight, keeping the DRAM stream continuous.

#define NT    8192
#define HALF  150
#define WIN   301
#define RPB   4

typedef unsigned long long u64;
typedef unsigned int u32;

__device__ __forceinline__ u32 absbits(float f) {
    return __float_as_uint(f) & 0x7fffffffu;
}
__device__ __forceinline__ u64 umax64(u64 a, u64 b) { return a > b ? a : b; }
__device__ __forceinline__ u64 shfl_xor_u64(u64 v, int d) {
    u32 lo = (u32)v, hi = (u32)(v >> 32);
    lo = __shfl_xor_sync(0xffffffffu, lo, d);
    hi = __shfl_xor_sync(0xffffffffu, hi, d);
    return ((u64)hi << 32) | lo;
}

// First index > bound inside tile whose absbits == val, or -1.
__device__ __forceinline__ int find_next(u32 em, int tile, int bound, int lane) {
    int base = tile * 128 + lane * 4;
    int rel = bound - base;                  // element j excluded iff j <= rel
    u32 emm = em;
    if (rel >= 3) emm = 0;
    else if (rel >= 0) emm &= (0xFu << (rel + 1));
    u32 bl = __ballot_sync(0xffffffffu, emm != 0);
    if (!bl) return -1;
    int lf = __ffs((int)bl) - 1;
    u32 pk = __shfl_sync(0xffffffffu, emm, lf);
    return tile * 128 + lf * 4 + (__ffs((int)pk) - 1);
}

__device__ __forceinline__ void select_row(const float* __restrict__ xr,
                                           const u32* __restrict__ tmx,
                                           float* __restrict__ out,
                                           int row, int nrows, int lane) {
    const u32 FULL = 0xffffffffu;
    u64 keys[2];
#pragma unroll
    for (int q = 0; q < 2; q++) {
        int t = lane + 32 * q;
        keys[q] = ((u64)tmx[t] << 32) | (u32)(~(u32)(t * 128));
    }
    u64 pend = 0;
    int pendIdx = -1;

    float rv0 = 0.0f, rv1 = 0.0f;
    int   ri0 = 0,    ri1 = 0;
    int found = 0;

    for (int it = 0; it < 192 && found < 2; it++) {
        u64 best = umax64(umax64(keys[0], keys[1]), pend);
#pragma unroll
        for (int s = 16; s > 0; s >>= 1) best = umax64(best, shfl_xor_u64(best, s));
        if (best == 0ull) break;

        bool wasPend = (best == pend && pend != 0ull);
        if (wasPend) pend = 0;
        if (keys[0] == best) keys[0] = 0;
        if (keys[1] == best) keys[1] = 0;

        u32 val = (u32)(best >> 32);
        int tile, idxV;
        if (wasPend) { idxV = pendIdx; tile = idxV >> 7; }
        else         { tile = (int)((~(u32)(best & 0xffffffffull)) >> 7); idxV = -1; }

        // rescan tile for occurrence chain (L1/L2-hot)
        float4 tv = ((const float4*)(xr + tile * 128))[lane];
        u32 em = (u32)(absbits(tv.x) == val)        |
                 ((u32)(absbits(tv.y) == val) << 1) |
                 ((u32)(absbits(tv.z) == val) << 2) |
                 ((u32)(absbits(tv.w) == val) << 3);
        if (!wasPend) idxV = find_next(em, tile, tile * 128 - 1, lane);
        int nxt = find_next(em, tile, idxV, lane);
        if (nxt >= 0) { pend = ((u64)val << 32) | (u32)(~(u32)nxt); pendIdx = nxt; }

        // verify idxV against window max using tile bounds (smem)
        int lo = max(idxV - HALF, 0);
        int hi = min(idxV + HALF, NT - 1);
        int ta = lo >> 7, tb = hi >> 7;
        int t = ta + lane;
        u32 tm = (t <= tb) ? tmx[t] : 0u;
        u32 bound = __reduce_max_sync(FULL, tm);

        bool accept = (bound <= val);
        if (!accept) {
            bool fullt = (t <= tb) && (t * 128 >= lo) && (t * 128 + 127 <= hi);
            if (__reduce_max_sync(FULL, fullt ? tm : 0u) > val) return_skip: ;
            if (__reduce_max_sync(FULL, fullt ? tm : 0u) > val) continue;
            u32 mb = 0;
            int base = idxV - HALF;
#pragma unroll
            for (int rr = 0; rr < 10; rr++) {
                int off = lane + 32 * rr;
                int p = min(max(base + off, 0), NT - 1);
                u32 xb = absbits(__ldg(xr + p));
                if (off < WIN) mb = max(mb, xb);
            }
            if (__reduce_max_sync(FULL, mb) > val) continue;
            accept = true;
        }

        if (found == 0) { rv0 = __uint_as_float(val); ri0 = idxV; }
        else            { rv1 = __uint_as_float(val); ri1 = idxV; }
        found++;
    }

    if (lane == 0) {
        if (found < 2) {
            rv1 = 0.0f;
            ri1 = (found >= 1 && ri0 == 0) ? 1 : 0;
        }
        out[row * 2 + 0] = rv0;
        out[row * 2 + 1] = rv1;
        out[(size_t)nrows * 2 + row * 2 + 0] = (float)ri0;
        out[(size_t)nrows * 2 + row * 2 + 1] = (float)ri1;
    }
}

__global__ void __launch_bounds__(512, 2)
detect_peaks_kernel(const float* __restrict__ x, float* __restrict__ out, int nrows) {
    __shared__ u32 tileMax[64];

    const int tid  = threadIdx.x;
    const int lane = tid & 31;
    const int warp = tid >> 5;
    const u32 FULL = 0xffffffffu;
    const int row0 = blockIdx.x * RPB;

    float4 v[4], vn[4];
    {
        const float4* src = (const float4*)(x + (size_t)row0 * NT);
#pragma unroll
        for (int k = 0; k < 4; k++) v[k] = src[tid + 512 * k];
    }

#pragma unroll
    for (int r = 0; r < RPB; r++) {
        const int row = row0 + r;

        // tile maxima for current row
#pragma unroll
        for (int k = 0; k < 4; k++) {
            float m01 = fmaxf(fabsf(v[k].x), fabsf(v[k].y));
            float m23 = fmaxf(fabsf(v[k].z), fabsf(v[k].w));
            float m   = fmaxf(m01, m23);
            u32 m1 = __reduce_max_sync(FULL, __float_as_uint(m));
            if (lane == 0) tileMax[warp + 16 * k] = m1;
        }
        __syncthreads();

        // prefetch next row (keeps LDGs in flight during selection)
        if (r + 1 < RPB) {
            const float4* srcn = (const float4*)(x + (size_t)(row + 1) * NT);
#pragma unroll
            for (int k = 0; k < 4; k++) vn[k] = srcn[tid + 512 * k];
        }

        if (warp == 0)
            select_row(x + (size_t)row * NT, tileMax, out, row, nrows, lane);
        __syncthreads();

#pragma unroll
        for (int k = 0; k < 4; k++) v[k] = vn[k];
    }
}

extern "C" void kernel_launch(void* const* d_in, const int* in_sizes, int n_in,
                              void* d_out, int out_size) {
    const float* x = (const float*)d_in[0];
    float* out = (float*)d_out;
    int nrows = in_sizes[0] / NT;   // 6144
    detect_peaks_kernel<<<nrows / RPB, 512>>>(x, out, nrows);
}

// round 10
// speedup vs baseline: 1.1693x; 1.1693x over previous
#include <cuda_runtime.h>
#include <cstdint>

// DetectPeaksTM: per-row sliding max (K=301) NMS + top-2 (value, index).
// Candidate-based (survivor == max of its aligned 128-tile). One row per
// 256-thread CTA; each thread front-batches 8 independent LDG.128s (MLP=8),
// then 8 REDUX produce the 64 tile maxima. Warp 0 recovers indices lazily
// and verifies candidates best-first via tile-max bounds.

#define NT    8192
#define HALF  150
#define WIN   301

typedef unsigned long long u64;
typedef unsigned int u32;

__device__ __forceinline__ u32 absbits(float f) {
    return __float_as_uint(f) & 0x7fffffffu;
}
__device__ __forceinline__ u64 umax64(u64 a, u64 b) { return a > b ? a : b; }
__device__ __forceinline__ u64 shfl_xor_u64(u64 v, int d) {
    u32 lo = (u32)v, hi = (u32)(v >> 32);
    lo = __shfl_xor_sync(0xffffffffu, lo, d);
    hi = __shfl_xor_sync(0xffffffffu, hi, d);
    return ((u64)hi << 32) | lo;
}

// First index > bound inside tile whose absbits == val, or -1.
__device__ __forceinline__ int find_next(u32 em, int tile, int bound, int lane) {
    int base = tile * 128 + lane * 4;
    int rel = bound - base;                  // element j excluded iff j <= rel
    u32 emm = em;
    if (rel >= 3) emm = 0;
    else if (rel >= 0) emm &= (0xFu << (rel + 1));
    u32 bl = __ballot_sync(0xffffffffu, emm != 0);
    if (!bl) return -1;
    int lf = __ffs((int)bl) - 1;
    u32 pk = __shfl_sync(0xffffffffu, emm, lf);
    return tile * 128 + lf * 4 + (__ffs((int)pk) - 1);
}

__global__ void __launch_bounds__(256)
detect_peaks_kernel(const float* __restrict__ x, float* __restrict__ out, int nrows) {
    __shared__ u32 tileMax[64];

    const int row  = blockIdx.x;
    const int tid  = threadIdx.x;
    const int lane = tid & 31;
    const int warp = tid >> 5;               // 0..7
    const u32 FULL = 0xffffffffu;

    const float* xr = x + (size_t)row * NT;
    const float4* src = (const float4*)xr;

    // ---- hot loop: 8 front-batched LDG.128 per thread, then tile maxima ----
    float4 v[8];
#pragma unroll
    for (int k = 0; k < 8; k++) v[k] = src[tid + 256 * k];

#pragma unroll
    for (int k = 0; k < 8; k++) {
        float m01 = fmaxf(fabsf(v[k].x), fabsf(v[k].y));
        float m23 = fmaxf(fabsf(v[k].z), fabsf(v[k].w));
        float m   = fmaxf(m01, m23);
        u32 m1 = __reduce_max_sync(FULL, __float_as_uint(m));
        if (lane == 0) tileMax[warp + 8 * k] = m1;   // tile = warp + 8k
    }
    __syncthreads();

    if (warp != 0) return;

    // ---- selection (warp 0): best-first over tile maxima ----
    u64 keys[2];
#pragma unroll
    for (int q = 0; q < 2; q++) {
        int t = lane + 32 * q;
        keys[q] = ((u64)tileMax[t] << 32) | (u32)(~(u32)(t * 128));
    }
    u64 pend = 0;        // at most one pending same-value occurrence (uniform)
    int pendIdx = -1;

    float rv0 = 0.0f, rv1 = 0.0f;
    int   ri0 = 0,    ri1 = 0;
    int found = 0;

    for (int it = 0; it < 192 && found < 2; it++) {
        u64 best = umax64(umax64(keys[0], keys[1]), pend);
#pragma unroll
        for (int s = 16; s > 0; s >>= 1) best = umax64(best, shfl_xor_u64(best, s));
        if (best == 0ull) break;

        bool wasPend = (best == pend && pend != 0ull);
        if (wasPend) pend = 0;
        if (keys[0] == best) keys[0] = 0;
        if (keys[1] == best) keys[1] = 0;

        u32 val = (u32)(best >> 32);
        int tile, idxV;
        if (wasPend) { idxV = pendIdx; tile = idxV >> 7; }
        else         { tile = (int)((~(u32)(best & 0xffffffffull)) >> 7); idxV = -1; }

        // rescan tile for occurrence chain (L1/L2-hot)
        float4 tv = ((const float4*)(xr + tile * 128))[lane];
        u32 em = (u32)(absbits(tv.x) == val)        |
                 ((u32)(absbits(tv.y) == val) << 1) |
                 ((u32)(absbits(tv.z) == val) << 2) |
                 ((u32)(absbits(tv.w) == val) << 3);
        if (!wasPend) idxV = find_next(em, tile, tile * 128 - 1, lane);
        int nxt = find_next(em, tile, idxV, lane);
        if (nxt >= 0) { pend = ((u64)val << 32) | (u32)(~(u32)nxt); pendIdx = nxt; }

        // verify idxV against window max using tile bounds (smem)
        int lo = max(idxV - HALF, 0);
        int hi = min(idxV + HALF, NT - 1);
        int ta = lo >> 7, tb = hi >> 7;
        int t = ta + lane;
        u32 tm = (t <= tb) ? tileMax[t] : 0u;
        u32 bound = __reduce_max_sync(FULL, tm);

        bool accept = (bound <= val);
        if (!accept) {
            bool fullt = (t <= tb) && (t * 128 >= lo) && (t * 128 + 127 <= hi);
            if (__reduce_max_sync(FULL, fullt ? tm : 0u) > val) continue;
            // ambiguous edge tiles: exact window max from gmem (rare)
            u32 mb = 0;
            int base = idxV - HALF;
#pragma unroll
            for (int rr = 0; rr < 10; rr++) {
                int off = lane + 32 * rr;
                int p = min(max(base + off, 0), NT - 1);
                u32 xb = absbits(__ldg(xr + p));
                if (off < WIN) mb = max(mb, xb);
            }
            if (__reduce_max_sync(FULL, mb) > val) continue;
            accept = true;
        }

        if (found == 0) { rv0 = __uint_as_float(val); ri0 = idxV; }
        else            { rv1 = __uint_as_float(val); ri1 = idxV; }
        found++;
    }

    if (lane == 0) {
        if (found < 2) {                 // <2 survivors: next-best score is 0
            rv1 = 0.0f;
            ri1 = (found >= 1 && ri0 == 0) ? 1 : 0;
        }
        out[row * 2 + 0] = rv0;
        out[row * 2 + 1] = rv1;
        out[(size_t)nrows * 2 + row * 2 + 0] = (float)ri0;
        out[(size_t)nrows * 2 + row * 2 + 1] = (float)ri1;
    }
}

extern "C" void kernel_launch(void* const* d_in, const int* in_sizes, int n_in,
                              void* d_out, int out_size) {
    const float* x = (const float*)d_in[0];
    float* out = (float*)d_out;
    int nrows = in_sizes[0] / NT;   // 6144
    detect_peaks_kernel<<<nrows, 256>>>(x, out, nrows);
}

// round 11
// speedup vs baseline: 1.1952x; 1.0221x over previous
#include <cuda_runtime.h>
#include <cstdint>

// DetectPeaksTM: per-row sliding max (K=301) NMS + top-2 (value, index).
// Candidate-based (survivor == max of its aligned 128-tile). One row per
// 256-thread CTA. The row (32 KB) is fetched with a single cp.async.bulk
// (TMA) into smem; tile maxima via REDUX from smem; warp 0 recovers indices
// and verifies candidates entirely from smem.

#define NT    8192
#define HALF  150
#define WIN   301

typedef unsigned long long u64;
typedef unsigned int u32;

__device__ __forceinline__ u32 absbits(float f) {
    return __float_as_uint(f) & 0x7fffffffu;
}
__device__ __forceinline__ u64 umax64(u64 a, u64 b) { return a > b ? a : b; }
__device__ __forceinline__ u64 shfl_xor_u64(u64 v, int d) {
    u32 lo = (u32)v, hi = (u32)(v >> 32);
    lo = __shfl_xor_sync(0xffffffffu, lo, d);
    hi = __shfl_xor_sync(0xffffffffu, hi, d);
    return ((u64)hi << 32) | lo;
}
__device__ __forceinline__ u32 smem_addr(const void* p) {
    u32 a;
    asm("{ .reg .u64 t; cvta.to.shared.u64 t, %1; cvt.u32.u64 %0, t; }"
        : "=r"(a) : "l"(p));
    return a;
}

// First index > bound inside tile whose absbits == val, or -1.
__device__ __forceinline__ int find_next(u32 em, int tile, int bound, int lane) {
    int base = tile * 128 + lane * 4;
    int rel = bound - base;                  // element j excluded iff j <= rel
    u32 emm = em;
    if (rel >= 3) emm = 0;
    else if (rel >= 0) emm &= (0xFu << (rel + 1));
    u32 bl = __ballot_sync(0xffffffffu, emm != 0);
    if (!bl) return -1;
    int lf = __ffs((int)bl) - 1;
    u32 pk = __shfl_sync(0xffffffffu, emm, lf);
    return tile * 128 + lf * 4 + (__ffs((int)pk) - 1);
}

__global__ void __launch_bounds__(256)
detect_peaks_kernel(const float* __restrict__ x, float* __restrict__ out, int nrows) {
    __shared__ alignas(16) float buf[NT];          // 32 KB row
    __shared__ u32 tileMax[64];
    __shared__ alignas(8) u64 mbar;

    const int row  = blockIdx.x;
    const int tid  = threadIdx.x;
    const int lane = tid & 31;
    const int warp = tid >> 5;               // 0..7
    const u32 FULL = 0xffffffffu;

    const u32 mb = smem_addr(&mbar);
    const u32 db = smem_addr(buf);

    if (tid == 0) {
        asm volatile("mbarrier.init.shared.b64 [%0], 1;" :: "r"(mb) : "memory");
    }
    __syncthreads();
    if (tid == 0) {
        asm volatile("mbarrier.arrive.expect_tx.shared.b64 _, [%0], %1;"
                     :: "r"(mb), "r"(NT * 4) : "memory");
        asm volatile("cp.async.bulk.shared::cta.global.mbarrier::complete_tx::bytes "
                     "[%0], [%1], %2, [%3];"
                     :: "r"(db), "l"(x + (size_t)row * NT), "r"(NT * 4), "r"(mb)
                     : "memory");
    }
    // wait (parity 0)
    {
        u32 done;
        asm volatile(
            "{\n\t.reg .pred p;\n\t"
            "mbarrier.try_wait.parity.acquire.cta.shared::cta.b64 p, [%1], 0;\n\t"
            "selp.b32 %0, 1, 0, p;\n\t}"
            : "=r"(done) : "r"(mb) : "memory");
        while (!done) {
            asm volatile(
                "{\n\t.reg .pred p;\n\t"
                "mbarrier.try_wait.parity.acquire.cta.shared::cta.b64 p, [%1], 0, 0x989680;\n\t"
                "selp.b32 %0, 1, 0, p;\n\t}"
                : "=r"(done) : "r"(mb) : "memory");
        }
    }

    // ---- tile maxima from smem ----
    const float4* sb = (const float4*)buf;
#pragma unroll
    for (int k = 0; k < 8; k++) {
        float4 v = sb[tid + 256 * k];
        float m01 = fmaxf(fabsf(v.x), fabsf(v.y));
        float m23 = fmaxf(fabsf(v.z), fabsf(v.w));
        float m   = fmaxf(m01, m23);
        u32 m1 = __reduce_max_sync(FULL, __float_as_uint(m));
        if (lane == 0) tileMax[warp + 8 * k] = m1;   // tile = warp + 8k
    }
    __syncthreads();

    if (warp != 0) return;

    // ---- selection (warp 0): best-first over tile maxima, all from smem ----
    u64 keys[2];
#pragma unroll
    for (int q = 0; q < 2; q++) {
        int t = lane + 32 * q;
        keys[q] = ((u64)tileMax[t] << 32) | (u32)(~(u32)(t * 128));
    }
    u64 pend = 0;        // at most one pending same-value occurrence (uniform)
    int pendIdx = -1;

    float rv0 = 0.0f, rv1 = 0.0f;
    int   ri0 = 0,    ri1 = 0;
    int found = 0;

    for (int it = 0; it < 192 && found < 2; it++) {
        u64 best = umax64(umax64(keys[0], keys[1]), pend);
#pragma unroll
        for (int s = 16; s > 0; s >>= 1) best = umax64(best, shfl_xor_u64(best, s));
        if (best == 0ull) break;

        bool wasPend = (best == pend && pend != 0ull);
        if (wasPend) pend = 0;
        if (keys[0] == best) keys[0] = 0;
        if (keys[1] == best) keys[1] = 0;

        u32 val = (u32)(best >> 32);
        int tile, idxV;
        if (wasPend) { idxV = pendIdx; tile = idxV >> 7; }
        else         { tile = (int)((~(u32)(best & 0xffffffffull)) >> 7); idxV = -1; }

        // rescan tile (smem) for occurrence chain
        float4 tv = sb[tile * 32 + lane];
        u32 em = (u32)(absbits(tv.x) == val)        |
                 ((u32)(absbits(tv.y) == val) << 1) |
                 ((u32)(absbits(tv.z) == val) << 2) |
                 ((u32)(absbits(tv.w) == val) << 3);
        if (!wasPend) idxV = find_next(em, tile, tile * 128 - 1, lane);
        int nxt = find_next(em, tile, idxV, lane);
        if (nxt >= 0) { pend = ((u64)val << 32) | (u32)(~(u32)nxt); pendIdx = nxt; }

        // verify idxV against window max using tile bounds (smem)
        int lo = max(idxV - HALF, 0);
        int hi = min(idxV + HALF, NT - 1);
        int ta = lo >> 7, tb = hi >> 7;
        int t = ta + lane;
        u32 tm = (t <= tb) ? tileMax[t] : 0u;
        u32 bound = __reduce_max_sync(FULL, tm);

        bool accept = (bound <= val);
        if (!accept) {
            bool fullt = (t <= tb) && (t * 128 >= lo) && (t * 128 + 127 <= hi);
            if (__reduce_max_sync(FULL, fullt ? tm : 0u) > val) continue;
            // ambiguous edge tiles: exact window max from smem
            u32 mbx = 0;
            int base = idxV - HALF;
#pragma unroll
            for (int rr = 0; rr < 10; rr++) {
                int off = lane + 32 * rr;
                int p = min(max(base + off, 0), NT - 1);
                u32 xb = absbits(buf[p]);
                if (off < WIN) mbx = max(mbx, xb);
            }
            if (__reduce_max_sync(FULL, mbx) > val) continue;
            accept = true;
        }

        if (found == 0) { rv0 = __uint_as_float(val); ri0 = idxV; }
        else            { rv1 = __uint_as_float(val); ri1 = idxV; }
        found++;
    }

    if (lane == 0) {
        if (found < 2) {                 // <2 survivors: next-best score is 0
            rv1 = 0.0f;
            ri1 = (found >= 1 && ri0 == 0) ? 1 : 0;
        }
        out[row * 2 + 0] = rv0;
        out[row * 2 + 1] = rv1;
        out[(size_t)nrows * 2 + row * 2 + 0] = (float)ri0;
        out[(size_t)nrows * 2 + row * 2 + 1] = (float)ri1;
    }
}

extern "C" void kernel_launch(void* const* d_in, const int* in_sizes, int n_in,
                              void* d_out, int out_size) {
    const float* x = (const float*)d_in[0];
    float* out = (float*)d_out;
    int nrows = in_sizes[0] / NT;   // 6144
    detect_peaks_kernel<<<nrows, 256>>>(x, out, nrows);
}